// round 5
// baseline (speedup 1.0000x reference)
#include <cuda_runtime.h>
#include <cuda_bf16.h>
#include <math.h>

#define MAXN 100000
#define MAXE 1600000
#define HDIM 64

// ---------------- scratch (static device globals; no allocation) -------------
__device__ int      g_counts [MAXN];
__device__ int      g_offsets[MAXN];
__device__ int      g_cursor [MAXN];
__device__ float    g_dis    [MAXN];
__device__ float2   g_epack  [MAXE];      // .x = __int_as_float(src), .y = norm
__device__ float    g_agg    [MAXN * HDIM];
__device__ float    g_h      [MAXN * HDIM];
__device__ int      g_bsum   [1024];
__device__ unsigned g_bar_count   = 0;    // grid barrier: arrive counter
__device__ unsigned g_bar_release = 0;    // grid barrier: monotonic epoch

// ---------------- fused preprocessing (persistent grid, software barrier) ----
// Phases: zero counts | count degrees | scan -> offsets/cursor/dis | fill CSR.
// Grid barrier: monotonic-epoch. At kernel entry no block has passed barrier 1,
// so every block reads the same base epoch. Counter resets each barrier, epoch
// increments by 4 per call -> state at rest between calls (deterministic).
__global__ void k_pre(const void* __restrict__ ei_raw, int n, int e) {
    __shared__ int ss[256];
    __shared__ int s_is64;

    const int t  = threadIdx.x;
    const int b  = blockIdx.x;
    const int T  = gridDim.x * 256;
    const int gt = b * 256 + t;

    unsigned base = 0;
    int nbar = 0;
    if (t == 0) {
        base = *(volatile unsigned*)&g_bar_release;
        // dtype probe: int64 indices read as int64 lie in [0,n); an int32
        // buffer misread as int64 packs two -> >= 2^32. Deterministic.
        const long long* e64 = (const long long*)ei_raw;
        int ok64 = 1;
        for (int k = 0; k < 8; k++) {
            long long v = e64[k];
            if (v < 0 || v >= (long long)n) ok64 = 0;
        }
        s_is64 = ok64;
    }
    __syncthreads();
    const int is64 = s_is64;

    auto gsync = [&]() {
        __threadfence();
        __syncthreads();
        if (t == 0) {
            nbar++;
            unsigned arr = atomicAdd(&g_bar_count, 1u);
            if (arr == (unsigned)gridDim.x - 1u) {
                atomicExch(&g_bar_count, 0u);
                __threadfence();
                atomicAdd(&g_bar_release, 1u);
            }
            while (*(volatile unsigned*)&g_bar_release < base + (unsigned)nbar) { }
        }
        __syncthreads();
    };

    // ---- phase 0: zero counts ----
    for (int i = gt; i < n; i += T) g_counts[i] = 0;
    gsync();

    // ---- phase 1: count in-degrees ----
    if (is64) {
        const long long* ei = (const long long*)ei_raw;
        for (int i = gt; i < e; i += T) {
            int d = (int)ei[(size_t)e + i];
            if ((unsigned)d < (unsigned)n) atomicAdd(&g_counts[d], 1);
        }
    } else {
        const int* ei = (const int*)ei_raw;
        for (int i = gt; i < e; i += T) {
            int d = ei[(size_t)e + i];
            if ((unsigned)d < (unsigned)n) atomicAdd(&g_counts[d], 1);
        }
    }
    gsync();

    // ---- phase 2: per-thread chunk sums + block scan -> block totals ----
    const int lenN = (n + T - 1) / T;
    const int lo = gt * lenN;
    const int hi = min(lo + lenN, n);
    int mysum = 0;
    for (int i = lo; i < hi; i++) mysum += g_counts[i];

    ss[t] = mysum;
    __syncthreads();
#pragma unroll
    for (int off = 1; off < 256; off <<= 1) {
        int v = (t >= off) ? ss[t - off] : 0;
        __syncthreads();
        ss[t] += v;
        __syncthreads();
    }
    const int thr_excl = ss[t] - mysum;     // exclusive prefix within block
    if (t == 0) g_bsum[b] = ss[255];        // block total
    gsync();

    // ---- phase 3: redundant scan of block totals -> offsets/cursor/dis ----
    {
        int bv = (t < gridDim.x) ? g_bsum[t] : 0;
        __syncthreads();                     // ss reuse barrier
        ss[t] = bv;
        __syncthreads();
#pragma unroll
        for (int off = 1; off < 256; off <<= 1) {
            int v = (t >= off) ? ss[t - off] : 0;
            __syncthreads();
            ss[t] += v;
            __syncthreads();
        }
        const int block_base = (b > 0) ? ss[b - 1] : 0;
        int off = block_base + thr_excl;
        for (int i = lo; i < hi; i++) {
            int c = g_counts[i];
            g_offsets[i] = off;
            g_cursor[i]  = off;
            g_dis[i]     = rsqrtf((float)(c + 1));
            off += c;
        }
    }
    gsync();

    // ---- phase 4: fill CSR (packed src+norm) ----
    if (is64) {
        const long long* ei = (const long long*)ei_raw;
        for (int i = gt; i < e; i += T) {
            int s = (int)ei[i];
            int d = (int)ei[(size_t)e + i];
            if ((unsigned)s < (unsigned)n && (unsigned)d < (unsigned)n) {
                int p = atomicAdd(&g_cursor[d], 1);
                g_epack[p] = make_float2(__int_as_float(s), g_dis[s] * g_dis[d]);
            }
        }
    } else {
        const int* ei = (const int*)ei_raw;
        for (int i = gt; i < e; i += T) {
            int s = ei[i];
            int d = ei[(size_t)e + i];
            if ((unsigned)s < (unsigned)n && (unsigned)d < (unsigned)n) {
                int p = atomicAdd(&g_cursor[d], 1);
                g_epack[p] = make_float2(__int_as_float(s), g_dis[s] * g_dis[d]);
            }
        }
    }
}

// ---------------- aggregation: g_agg = A_norm_with_selfloops * in ------------
// Warp per destination node; lane covers feature cols {2*lane, 2*lane+1} as a
// float2 -> one LDG.64 per edge per warp (full 256B row in one instruction).
// Metadata (src,norm) is one packed broadcast LDG.64; unroll-by-4 keeps 4
// gathers in flight (MLP=4).
__global__ void k_agg(const float* __restrict__ xin, int n, int from_x) {
    int warp = (blockIdx.x * blockDim.x + threadIdx.x) >> 5;
    int lane = threadIdx.x & 31;
    if (warp >= n) return;

    const float2* __restrict__ in2 =
        (const float2*)(from_x ? xin : (const float*)g_h);

    float di    = g_dis[warp];
    float selfc = di * di;

    float2 r = __ldg(&in2[(size_t)warp * 32 + lane]);
    float acc0 = r.x * selfc;
    float acc1 = r.y * selfc;

    int start = g_offsets[warp];
    int cnt   = g_counts[warp];
    int j = 0;
    for (; j + 4 <= cnt; j += 4) {
        float2 m0 = __ldg(&g_epack[start + j]);
        float2 m1 = __ldg(&g_epack[start + j + 1]);
        float2 m2 = __ldg(&g_epack[start + j + 2]);
        float2 m3 = __ldg(&g_epack[start + j + 3]);
        float2 v0 = __ldg(&in2[(size_t)__float_as_int(m0.x) * 32 + lane]);
        float2 v1 = __ldg(&in2[(size_t)__float_as_int(m1.x) * 32 + lane]);
        float2 v2 = __ldg(&in2[(size_t)__float_as_int(m2.x) * 32 + lane]);
        float2 v3 = __ldg(&in2[(size_t)__float_as_int(m3.x) * 32 + lane]);
        acc0 = fmaf(m0.y, v0.x, acc0);  acc1 = fmaf(m0.y, v0.y, acc1);
        acc0 = fmaf(m1.y, v1.x, acc0);  acc1 = fmaf(m1.y, v1.y, acc1);
        acc0 = fmaf(m2.y, v2.x, acc0);  acc1 = fmaf(m2.y, v2.y, acc1);
        acc0 = fmaf(m3.y, v3.x, acc0);  acc1 = fmaf(m3.y, v3.y, acc1);
    }
    for (; j < cnt; j++) {
        float2 m = __ldg(&g_epack[start + j]);
        float2 v = __ldg(&in2[(size_t)__float_as_int(m.x) * 32 + lane]);
        acc0 = fmaf(m.y, v.x, acc0);
        acc1 = fmaf(m.y, v.y, acc1);
    }
    ((float2*)g_agg)[(size_t)warp * 32 + lane] = make_float2(acc0, acc1);
}

// ---------------- GEMM: out = [relu](g_agg @ W + b),  g_agg: n x 64 ----------
__global__ void k_gemm(const float* __restrict__ W, const float* __restrict__ b,
                       float* __restrict__ outp, int n, int do_relu, int to_out) {
    __shared__ float Ws[64 * 64];
    __shared__ float xs[64 * 68];
    const float* __restrict__ in  = (const float*)g_agg;
    float* __restrict__       out = to_out ? outp : (float*)g_h;

    int t = threadIdx.x;
    int row0 = blockIdx.x * 64;

    for (int i = t; i < 4096; i += 256) Ws[i] = W[i];
    for (int i = t; i < 4096; i += 256) {
        int r = i >> 6, k = i & 63;
        float v = (row0 + r < n) ? in[(size_t)(row0 + r) * HDIM + k] : 0.0f;
        xs[k * 68 + r] = v;
    }
    __syncthreads();

    int tx = t & 15, ty = t >> 4;
    int c0 = tx * 4, r0 = ty * 4;

    float acc[4][4] = {};
#pragma unroll
    for (int k = 0; k < 64; k++) {
        float4 xv = *(const float4*)&xs[k * 68 + r0];
        float4 wv = *(const float4*)&Ws[k * 64 + c0];
        acc[0][0] = fmaf(xv.x, wv.x, acc[0][0]);
        acc[0][1] = fmaf(xv.x, wv.y, acc[0][1]);
        acc[0][2] = fmaf(xv.x, wv.z, acc[0][2]);
        acc[0][3] = fmaf(xv.x, wv.w, acc[0][3]);
        acc[1][0] = fmaf(xv.y, wv.x, acc[1][0]);
        acc[1][1] = fmaf(xv.y, wv.y, acc[1][1]);
        acc[1][2] = fmaf(xv.y, wv.z, acc[1][2]);
        acc[1][3] = fmaf(xv.y, wv.w, acc[1][3]);
        acc[2][0] = fmaf(xv.z, wv.x, acc[2][0]);
        acc[2][1] = fmaf(xv.z, wv.y, acc[2][1]);
        acc[2][2] = fmaf(xv.z, wv.z, acc[2][2]);
        acc[2][3] = fmaf(xv.z, wv.w, acc[2][3]);
        acc[3][0] = fmaf(xv.w, wv.x, acc[3][0]);
        acc[3][1] = fmaf(xv.w, wv.y, acc[3][1]);
        acc[3][2] = fmaf(xv.w, wv.z, acc[3][2]);
        acc[3][3] = fmaf(xv.w, wv.w, acc[3][3]);
    }

    float4 bv = *(const float4*)&b[c0];
#pragma unroll
    for (int rr = 0; rr < 4; rr++) {
        int r = row0 + r0 + rr;
        if (r < n) {
            float4 o;
            o.x = acc[rr][0] + bv.x;
            o.y = acc[rr][1] + bv.y;
            o.z = acc[rr][2] + bv.z;
            o.w = acc[rr][3] + bv.w;
            if (do_relu) {
                o.x = fmaxf(o.x, 0.0f);
                o.y = fmaxf(o.y, 0.0f);
                o.z = fmaxf(o.z, 0.0f);
                o.w = fmaxf(o.w, 0.0f);
            }
            *(float4*)&out[(size_t)r * HDIM + c0] = o;
        }
    }
}

// ---------------- launch ------------------------------------------------------
extern "C" void kernel_launch(void* const* d_in, const int* in_sizes, int n_in,
                              void* d_out, int out_size) {
    const float* x  = (const float*)d_in[0];
    const void*  ei = d_in[1];
    // d_in[2] = edge_features (unused by GCNConv reference)
    const float* W1 = (const float*)d_in[3];
    const float* b1 = (const float*)d_in[4];
    const float* W2 = (const float*)d_in[5];
    const float* b2 = (const float*)d_in[6];
    const float* W3 = (const float*)d_in[7];
    const float* b3 = (const float*)d_in[8];
    float* outp = (float*)d_out;

    int N = in_sizes[0] / HDIM;
    int E = in_sizes[1] / 2;

    // Persistent grid: one block per SM (all co-resident -> grid barrier safe).
    static int sm_count = 0;
    if (sm_count == 0) {
        cudaDeviceGetAttribute(&sm_count, cudaDevAttrMultiProcessorCount, 0);
        if (sm_count <= 0 || sm_count > 1024) sm_count = 148;
    }

    k_pre<<<sm_count, 256>>>(ei, N, E);

    int agg_blocks  = (N * 32 + 255) / 256;
    int gemm_blocks = (N + 63) / 64;

    k_agg <<<agg_blocks, 256>>>(x, N, 1);
    k_gemm<<<gemm_blocks, 256>>>(W1, b1, outp, N, 1, 0);

    k_agg <<<agg_blocks, 256>>>(x, N, 0);
    k_gemm<<<gemm_blocks, 256>>>(W2, b2, outp, N, 1, 0);

    k_agg <<<agg_blocks, 256>>>(x, N, 0);
    k_gemm<<<gemm_blocks, 256>>>(W3, b3, outp, N, 0, 1);
}

// round 6
// speedup vs baseline: 1.1199x; 1.1199x over previous
#include <cuda_runtime.h>
#include <cuda_bf16.h>
#include <math.h>

#define MAXN 100000
#define MAXE 1600000
#define HDIM 64

// ---------------- scratch (static device globals; no allocation) -------------
__device__ int    g_counts [MAXN];
__device__ int    g_offsets[MAXN];
__device__ int    g_cursor [MAXN];
__device__ float  g_dis    [MAXN];
__device__ float2 g_epack  [MAXE];        // .x = __int_as_float(src), .y = norm
__device__ float  g_agg    [MAXN * HDIM];
__device__ float  g_h      [MAXN * HDIM];
__device__ int    g_bsum   [512];
__device__ int    g_is64;   // 1 if edge_index buffer is int64, 0 if int32

// ---------------- zero + dtype probe -----------------------------------------
// True int64 indices read as int64 lie in [0, n). An int32 buffer misread as
// int64 packs two indices per word -> values >= 2^32. Deterministic.
__global__ void k_zero_probe(const void* __restrict__ ei_raw, int n) {
    int i = blockIdx.x * blockDim.x + threadIdx.x;
    if (i < n) g_counts[i] = 0;
    if (i == 0) {
        const long long* e64 = (const long long*)ei_raw;
        int ok64 = 1;
        for (int k = 0; k < 8; k++) {
            long long v = e64[k];
            if (v < 0 || v >= (long long)n) ok64 = 0;
        }
        g_is64 = ok64;
    }
}

// ---------------- count in-degrees (vectorized: 2 edges/thread) --------------
// edge_index is (2, E) row-major: [0..E) = src, [E..2E) = dst. E is even and
// both halves are 16B-aligned, so longlong2/int2 vector loads are safe.
__global__ void k_count(const void* __restrict__ ei_raw, int e, int n) {
    int i = blockIdx.x * blockDim.x + threadIdx.x;   // pair index
    if (2 * i >= e) return;
    int d0, d1;
    if (g_is64) {
        const longlong2* p = (const longlong2*)((const long long*)ei_raw + e);
        longlong2 v = __ldg(&p[i]);
        d0 = (int)v.x; d1 = (int)v.y;
    } else {
        const int2* p = (const int2*)((const int*)ei_raw + e);
        int2 v = __ldg(&p[i]);
        d0 = v.x; d1 = v.y;
    }
    if ((unsigned)d0 < (unsigned)n) atomicAdd(&g_counts[d0], 1);
    if ((unsigned)d1 < (unsigned)n) atomicAdd(&g_counts[d1], 1);
}

// Block-level exclusive scan of counts (512/block); also dis = rsqrt(deg+1)
__global__ void k_scan1(int n) {
    __shared__ int s[512];
    int t = threadIdx.x;
    int i = blockIdx.x * 512 + t;
    int v = (i < n) ? g_counts[i] : 0;
    s[t] = v;
    __syncthreads();
#pragma unroll
    for (int off = 1; off < 512; off <<= 1) {
        int tv = (t >= off) ? s[t - off] : 0;
        __syncthreads();
        s[t] += tv;
        __syncthreads();
    }
    if (i < n) {
        g_offsets[i] = s[t] - v;                  // exclusive within block
        g_dis[i]     = rsqrtf((float)(v + 1));    // deg includes self-loop
    }
    if (t == 511) g_bsum[blockIdx.x] = s[511];
}

// Exclusive scan of per-block sums (nb <= 512), single block
__global__ void k_scan2(int nb) {
    __shared__ int s[512];
    int t = threadIdx.x;
    int v = (t < nb) ? g_bsum[t] : 0;
    s[t] = v;
    __syncthreads();
#pragma unroll
    for (int off = 1; off < 512; off <<= 1) {
        int tv = (t >= off) ? s[t - off] : 0;
        __syncthreads();
        s[t] += tv;
        __syncthreads();
    }
    if (t < nb) g_bsum[t] = s[t] - v;             // exclusive
}

__global__ void k_scan3(int n) {
    int i = blockIdx.x * 512 + threadIdx.x;
    if (i < n) {
        int o = g_offsets[i] + g_bsum[blockIdx.x];
        g_offsets[i] = o;
        g_cursor[i]  = o;
    }
}

// ---------------- fill CSR (vectorized: 2 edges/thread) ----------------------
__global__ void k_fill(const void* __restrict__ ei_raw, int e, int n) {
    int i = blockIdx.x * blockDim.x + threadIdx.x;   // pair index
    if (2 * i >= e) return;
    int s0, s1, d0, d1;
    if (g_is64) {
        const longlong2* ps = (const longlong2*)((const long long*)ei_raw);
        const longlong2* pd = (const longlong2*)((const long long*)ei_raw + e);
        longlong2 vs = __ldg(&ps[i]);
        longlong2 vd = __ldg(&pd[i]);
        s0 = (int)vs.x; s1 = (int)vs.y; d0 = (int)vd.x; d1 = (int)vd.y;
    } else {
        const int2* ps = (const int2*)((const int*)ei_raw);
        const int2* pd = (const int2*)((const int*)ei_raw + e);
        int2 vs = __ldg(&ps[i]);
        int2 vd = __ldg(&pd[i]);
        s0 = vs.x; s1 = vs.y; d0 = vd.x; d1 = vd.y;
    }
    if ((unsigned)s0 < (unsigned)n && (unsigned)d0 < (unsigned)n) {
        int p = atomicAdd(&g_cursor[d0], 1);
        g_epack[p] = make_float2(__int_as_float(s0), g_dis[s0] * g_dis[d0]);
    }
    if ((unsigned)s1 < (unsigned)n && (unsigned)d1 < (unsigned)n) {
        int p = atomicAdd(&g_cursor[d1], 1);
        g_epack[p] = make_float2(__int_as_float(s1), g_dis[s1] * g_dis[d1]);
    }
}

// ---------------- aggregation: g_agg = A_norm_with_selfloops * in ------------
// Warp per destination node; lane covers feature cols {2*lane, 2*lane+1} as a
// float2 (full 256B row in one LDG.64 per warp). Unroll-by-8 front-batches 8
// metadata loads + 8 gathers -> ~16 outstanding loads per warp (latency-bound
// per R5 ncu: L1=45%, issue=39%, no pipe saturated).
__global__ void k_agg(const float* __restrict__ xin, int n, int from_x) {
    int warp = (blockIdx.x * blockDim.x + threadIdx.x) >> 5;
    int lane = threadIdx.x & 31;
    if (warp >= n) return;

    const float2* __restrict__ in2 =
        (const float2*)(from_x ? xin : (const float*)g_h);

    float di    = g_dis[warp];
    float selfc = di * di;

    float2 r = __ldg(&in2[(size_t)warp * 32 + lane]);
    float acc0 = r.x * selfc;
    float acc1 = r.y * selfc;

    int start = g_offsets[warp];
    int cnt   = g_counts[warp];
    int j = 0;
    for (; j + 8 <= cnt; j += 8) {
        const float2* mp = &g_epack[start + j];
        float2 m0 = __ldg(mp);
        float2 m1 = __ldg(mp + 1);
        float2 m2 = __ldg(mp + 2);
        float2 m3 = __ldg(mp + 3);
        float2 m4 = __ldg(mp + 4);
        float2 m5 = __ldg(mp + 5);
        float2 m6 = __ldg(mp + 6);
        float2 m7 = __ldg(mp + 7);
        float2 v0 = __ldg(&in2[(size_t)__float_as_int(m0.x) * 32 + lane]);
        float2 v1 = __ldg(&in2[(size_t)__float_as_int(m1.x) * 32 + lane]);
        float2 v2 = __ldg(&in2[(size_t)__float_as_int(m2.x) * 32 + lane]);
        float2 v3 = __ldg(&in2[(size_t)__float_as_int(m3.x) * 32 + lane]);
        float2 v4 = __ldg(&in2[(size_t)__float_as_int(m4.x) * 32 + lane]);
        float2 v5 = __ldg(&in2[(size_t)__float_as_int(m5.x) * 32 + lane]);
        float2 v6 = __ldg(&in2[(size_t)__float_as_int(m6.x) * 32 + lane]);
        float2 v7 = __ldg(&in2[(size_t)__float_as_int(m7.x) * 32 + lane]);
        acc0 = fmaf(m0.y, v0.x, acc0);  acc1 = fmaf(m0.y, v0.y, acc1);
        acc0 = fmaf(m1.y, v1.x, acc0);  acc1 = fmaf(m1.y, v1.y, acc1);
        acc0 = fmaf(m2.y, v2.x, acc0);  acc1 = fmaf(m2.y, v2.y, acc1);
        acc0 = fmaf(m3.y, v3.x, acc0);  acc1 = fmaf(m3.y, v3.y, acc1);
        acc0 = fmaf(m4.y, v4.x, acc0);  acc1 = fmaf(m4.y, v4.y, acc1);
        acc0 = fmaf(m5.y, v5.x, acc0);  acc1 = fmaf(m5.y, v5.y, acc1);
        acc0 = fmaf(m6.y, v6.x, acc0);  acc1 = fmaf(m6.y, v6.y, acc1);
        acc0 = fmaf(m7.y, v7.x, acc0);  acc1 = fmaf(m7.y, v7.y, acc1);
    }
    for (; j < cnt; j++) {
        float2 m = __ldg(&g_epack[start + j]);
        float2 v = __ldg(&in2[(size_t)__float_as_int(m.x) * 32 + lane]);
        acc0 = fmaf(m.y, v.x, acc0);
        acc1 = fmaf(m.y, v.y, acc1);
    }
    ((float2*)g_agg)[(size_t)warp * 32 + lane] = make_float2(acc0, acc1);
}

// ---------------- GEMM: out = [relu](g_agg @ W + b),  g_agg: n x 64 ----------
__global__ void k_gemm(const float* __restrict__ W, const float* __restrict__ b,
                       float* __restrict__ outp, int n, int do_relu, int to_out) {
    __shared__ float Ws[64 * 64];
    __shared__ float xs[64 * 68];
    const float* __restrict__ in  = (const float*)g_agg;
    float* __restrict__       out = to_out ? outp : (float*)g_h;

    int t = threadIdx.x;
    int row0 = blockIdx.x * 64;

    for (int i = t; i < 4096; i += 256) Ws[i] = W[i];
    for (int i = t; i < 4096; i += 256) {
        int r = i >> 6, k = i & 63;
        float v = (row0 + r < n) ? in[(size_t)(row0 + r) * HDIM + k] : 0.0f;
        xs[k * 68 + r] = v;
    }
    __syncthreads();

    int tx = t & 15, ty = t >> 4;
    int c0 = tx * 4, r0 = ty * 4;

    float acc[4][4] = {};
#pragma unroll
    for (int k = 0; k < 64; k++) {
        float4 xv = *(const float4*)&xs[k * 68 + r0];
        float4 wv = *(const float4*)&Ws[k * 64 + c0];
        acc[0][0] = fmaf(xv.x, wv.x, acc[0][0]);
        acc[0][1] = fmaf(xv.x, wv.y, acc[0][1]);
        acc[0][2] = fmaf(xv.x, wv.z, acc[0][2]);
        acc[0][3] = fmaf(xv.x, wv.w, acc[0][3]);
        acc[1][0] = fmaf(xv.y, wv.x, acc[1][0]);
        acc[1][1] = fmaf(xv.y, wv.y, acc[1][1]);
        acc[1][2] = fmaf(xv.y, wv.z, acc[1][2]);
        acc[1][3] = fmaf(xv.y, wv.w, acc[1][3]);
        acc[2][0] = fmaf(xv.z, wv.x, acc[2][0]);
        acc[2][1] = fmaf(xv.z, wv.y, acc[2][1]);
        acc[2][2] = fmaf(xv.z, wv.z, acc[2][2]);
        acc[2][3] = fmaf(xv.z, wv.w, acc[2][3]);
        acc[3][0] = fmaf(xv.w, wv.x, acc[3][0]);
        acc[3][1] = fmaf(xv.w, wv.y, acc[3][1]);
        acc[3][2] = fmaf(xv.w, wv.z, acc[3][2]);
        acc[3][3] = fmaf(xv.w, wv.w, acc[3][3]);
    }

    float4 bv = *(const float4*)&b[c0];
#pragma unroll
    for (int rr = 0; rr < 4; rr++) {
        int r = row0 + r0 + rr;
        if (r < n) {
            float4 o;
            o.x = acc[rr][0] + bv.x;
            o.y = acc[rr][1] + bv.y;
            o.z = acc[rr][2] + bv.z;
            o.w = acc[rr][3] + bv.w;
            if (do_relu) {
                o.x = fmaxf(o.x, 0.0f);
                o.y = fmaxf(o.y, 0.0f);
                o.z = fmaxf(o.z, 0.0f);
                o.w = fmaxf(o.w, 0.0f);
            }
            *(float4*)&out[(size_t)r * HDIM + c0] = o;
        }
    }
}

// ---------------- launch ------------------------------------------------------
extern "C" void kernel_launch(void* const* d_in, const int* in_sizes, int n_in,
                              void* d_out, int out_size) {
    const float* x  = (const float*)d_in[0];
    const void*  ei = d_in[1];
    // d_in[2] = edge_features (unused by GCNConv reference)
    const float* W1 = (const float*)d_in[3];
    const float* b1 = (const float*)d_in[4];
    const float* W2 = (const float*)d_in[5];
    const float* b2 = (const float*)d_in[6];
    const float* W3 = (const float*)d_in[7];
    const float* b3 = (const float*)d_in[8];
    float* outp = (float*)d_out;

    int N = in_sizes[0] / HDIM;
    int E = in_sizes[1] / 2;
    int Ep = E / 2;                      // edge pairs (E is even)

    int nb = (N + 511) / 512;

    // ---- dtype probe + CSR build ----
    k_zero_probe<<<(N + 255) / 256, 256>>>(ei, N);
    k_count<<<(Ep + 255) / 256, 256>>>(ei, E, N);
    k_scan1<<<nb, 512>>>(N);
    k_scan2<<<1, 512>>>(nb);
    k_scan3<<<nb, 512>>>(N);
    k_fill<<<(Ep + 255) / 256, 256>>>(ei, E, N);

    int agg_blocks  = (N * 32 + 255) / 256;
    int gemm_blocks = (N + 63) / 64;

    // ---- layer 1 ----
    k_agg <<<agg_blocks, 256>>>(x, N, 1);
    k_gemm<<<gemm_blocks, 256>>>(W1, b1, outp, N, 1, 0);

    // ---- layer 2 ----
    k_agg <<<agg_blocks, 256>>>(x, N, 0);
    k_gemm<<<gemm_blocks, 256>>>(W2, b2, outp, N, 1, 0);

    // ---- layer 3 (no relu, direct to d_out) ----
    k_agg <<<agg_blocks, 256>>>(x, N, 0);
    k_gemm<<<gemm_blocks, 256>>>(W3, b3, outp, N, 0, 1);
}